// round 8
// baseline (speedup 1.0000x reference)
#include <cuda_runtime.h>
#include <cuda_fp16.h>
#include <cstdint>

// Problem dims (fixed by the dataset)
#define MDIM 4096
#define NDIM 4096
#define KDIM 4096
#define GS   128

// ---------------- scratch (allocation-free rule: __device__ globals) --------
__device__ __half g_Ah[(size_t)MDIM * KDIM];   // A in fp16, row-major [M,K]
__device__ __half g_Wt[(size_t)NDIM * KDIM];   // W^T in fp16, row-major [N,K]

// ---------------- helpers ----------------------------------------------------
__device__ __forceinline__ uint32_t smem_u32(const void* p) {
    uint32_t a;
    asm("{ .reg .u64 t; cvta.to.shared.u64 t, %1; cvt.u32.u64 %0, t; }"
        : "=r"(a) : "l"(p));
    return a;
}

__device__ __forceinline__ uint32_t sw128(uint32_t o) {
    return o ^ ((o >> 3) & 0x70);
}

#define CP_ASYNC16(dst, src) \
    asm volatile("cp.async.cg.shared.global [%0], [%1], 16;" :: "r"(dst), "l"(src) : "memory")
#define CP_COMMIT() asm volatile("cp.async.commit_group;" ::: "memory")
template <int N>
__device__ __forceinline__ void cp_wait() {
    asm volatile("cp.async.wait_group %0;" :: "n"(N) : "memory");
}

__device__ __forceinline__ void ldsm_x4(uint32_t (&r)[4], uint32_t addr) {
    asm volatile("ldmatrix.sync.aligned.m8n8.x4.shared.b16 {%0,%1,%2,%3}, [%4];"
                 : "=r"(r[0]), "=r"(r[1]), "=r"(r[2]), "=r"(r[3]) : "r"(addr));
}

__device__ __forceinline__ void mma_16816(float (&d)[4], const uint32_t (&a)[4],
                                          const uint32_t b0, const uint32_t b1) {
    asm volatile(
        "mma.sync.aligned.m16n8k16.row.col.f32.f16.f16.f32 "
        "{%0,%1,%2,%3}, {%4,%5,%6,%7}, {%8,%9}, {%0,%1,%2,%3};"
        : "+f"(d[0]), "+f"(d[1]), "+f"(d[2]), "+f"(d[3])
        : "r"(a[0]), "r"(a[1]), "r"(a[2]), "r"(a[3]), "r"(b0), "r"(b1));
}

// ---------------- kernel 1: fused prep ---------------------------------------
// Blocks [0, 8192): A fp32 -> fp16.
// Blocks [8192, 12288): dequant+transpose q -> Wt[n][k] fp16.
static constexpr int CONV_BLOCKS = 8192;
static constexpr int DEQ_BLOCKS = (KDIM / 64) * (NDIM / 64);   // 4096
__global__ void __launch_bounds__(256) prep_kernel(const float4* __restrict__ A,
                                                   const int* __restrict__ q,
                                                   const float* __restrict__ s) {
    int t = threadIdx.x;
    if (blockIdx.x < CONV_BLOCKS) {
        size_t i = (size_t)blockIdx.x * 256 + t;   // 8 floats each
        float4 f0 = A[2 * i];
        float4 f1 = A[2 * i + 1];
        __half2 h[4];
        h[0] = __floats2half2_rn(f0.x, f0.y);
        h[1] = __floats2half2_rn(f0.z, f0.w);
        h[2] = __floats2half2_rn(f1.x, f1.y);
        h[3] = __floats2half2_rn(f1.z, f1.w);
        *reinterpret_cast<uint4*>(g_Ah + 8 * i) = *reinterpret_cast<uint4*>(h);
        return;
    }

    __shared__ float s_sc[64];
    __shared__ __half s_t[64][72];  // [n_local][k_local], padded

    int b = blockIdx.x - CONV_BLOCKS;
    int k0 = (b & 63) * 64;
    int n0 = (b >> 6) * 64;

    if (t < 64) s_sc[t] = s[(size_t)(k0 / GS) * NDIM + n0 + t];
    __syncthreads();

    #pragma unroll
    for (int it = 0; it < 2; it++) {
        int v = t + it * 256;
        int kl = v >> 3;
        int w = v & 7;
        uint32_t qw = (uint32_t)q[(size_t)(k0 + kl) * (NDIM / 8) + (n0 >> 3) + w];
        #pragma unroll
        for (int bb = 0; bb < 8; bb++) {
            int nib = (int)((qw >> (4 * bb)) & 0xFu);
            float val = (float)(nib - 8) * s_sc[w * 8 + bb];
            s_t[w * 8 + bb][kl] = __float2half_rn(val);
        }
    }
    __syncthreads();

    int nl = t >> 2;
    int c = (t & 3) * 16;
    const uint4* src = reinterpret_cast<const uint4*>(&s_t[nl][c]);
    uint4* dst = reinterpret_cast<uint4*>(&g_Wt[(size_t)(n0 + nl) * KDIM + k0 + c]);
    dst[0] = src[0];
    dst[1] = src[1];
}

// ---------------- kernel 2: HMMA f16 GEMM ------------------------------------
// CTA tile 128x128, BK=64, 3-stage cp.async pipeline, 8 warps (64x32 each),
// 2 CTAs/SM, ONE __syncthreads per chunk, register double-buffered fragments.
static constexpr int BK = 64;
static constexpr int NSTAGES = 3;
static constexpr int NCHUNK = KDIM / BK;            // 64
static constexpr int TILE_BYTES = 128 * BK * 2;     // 16 KB per operand per stage
static constexpr uint32_t STAGE_BYTES = 2 * TILE_BYTES;          // 32 KB
static constexpr uint32_t SMEM_TOTAL = NSTAGES * STAGE_BYTES;    // 96 KB

__device__ __forceinline__ void load_stage(uint32_t sb, int stage, int chunk,
                                           int m0, int n0, int t) {
    uint32_t a_s = sb + stage * STAGE_BYTES;
    uint32_t b_s = a_s + TILE_BYTES;
    size_t kbase = (size_t)chunk * BK;
    #pragma unroll
    for (int j = 0; j < 4; j++) {
        int v = t + 256 * j;       // 0..1023
        int r = v >> 3;            // row 0..127
        int c = v & 7;             // 16B chunk within 128B row
        uint32_t off = sw128((uint32_t)(r * 128 + c * 16));
        const __half* asrc = g_Ah + (size_t)(m0 + r) * KDIM + kbase + c * 8;
        const __half* bsrc = g_Wt + (size_t)(n0 + r) * KDIM + kbase + c * 8;
        CP_ASYNC16(a_s + off, asrc);
        CP_ASYNC16(b_s + off, bsrc);
    }
}

__global__ void __launch_bounds__(256, 2)
gemm_kernel(float* __restrict__ out) {
    extern __shared__ char smem[];
    uint32_t sb = smem_u32(smem);
    int t = threadIdx.x;
    int wid = t >> 5;
    int lane = t & 31;
    int n0 = blockIdx.x * 128;
    int m0 = blockIdx.y * 128;

    // warp tiling: 2 (M) x 4 (N) warps; warp tile 64 x 32
    int warpM = (wid & 1) * 64;
    int warpN = (wid >> 1) * 32;

    // per-lane ldmatrix address components
    int tt = lane >> 3;        // matrix index within x4
    int lr = lane & 7;         // row within 8x8 matrix
    int arow = warpM + (tt & 1) * 8 + lr;
    int akoff = (tt >> 1) * 16;       // bytes
    int brow = warpN + (tt >> 1) * 8 + lr;
    int bkoff = (tt & 1) * 16;        // bytes

    float acc[4][4][4];
    #pragma unroll
    for (int mi = 0; mi < 4; mi++)
        #pragma unroll
        for (int ni = 0; ni < 4; ni++)
            #pragma unroll
            for (int e = 0; e < 4; e++) acc[mi][ni][e] = 0.0f;

    // prologue: fill stages 0,1 (chunks 0,1)
    load_stage(sb, 0, 0, m0, n0, t);
    CP_COMMIT();
    load_stage(sb, 1, 1, m0, n0, t);
    CP_COMMIT();

    uint32_t afrag[2][4][4];
    uint32_t bfrag[2][2][4];

    int stage = 0;
    for (int i = 0; i < NCHUNK; i++) {
        cp_wait<NSTAGES - 2>();   // chunk i resident (per-thread)
        __syncthreads();          // stage-i visible to all; stage (i+2)%3 free

        // prefetch chunk i+2 into the just-freed stage
        int pf = i + NSTAGES - 1;
        if (pf < NCHUNK) {
            int pstage = stage + 2 >= NSTAGES ? stage + 2 - NSTAGES : stage + 2;
            load_stage(sb, pstage, pf, m0, n0, t);
        }
        CP_COMMIT();

        uint32_t a_s = sb + stage * STAGE_BYTES;
        uint32_t b_s = a_s + TILE_BYTES;

        // frag pipeline: load kk=0, then overlap load kk+1 with mma kk
        #pragma unroll
        for (int mi = 0; mi < 4; mi++)
            ldsm_x4(afrag[0][mi], a_s + sw128((uint32_t)((arow + mi * 16) * 128 + akoff)));
        #pragma unroll
        for (int np = 0; np < 2; np++)
            ldsm_x4(bfrag[0][np], b_s + sw128((uint32_t)((brow + np * 16) * 128 + bkoff)));

        #pragma unroll
        for (int kk = 0; kk < 4; kk++) {
            int cur = kk & 1;
            int nxt = cur ^ 1;
            if (kk < 3) {
                #pragma unroll
                for (int mi = 0; mi < 4; mi++)
                    ldsm_x4(afrag[nxt][mi],
                            a_s + sw128((uint32_t)((arow + mi * 16) * 128 + (kk + 1) * 32 + akoff)));
                #pragma unroll
                for (int np = 0; np < 2; np++)
                    ldsm_x4(bfrag[nxt][np],
                            b_s + sw128((uint32_t)((brow + np * 16) * 128 + (kk + 1) * 32 + bkoff)));
            }
            #pragma unroll
            for (int mi = 0; mi < 4; mi++) {
                #pragma unroll
                for (int ni = 0; ni < 4; ni++) {
                    mma_16816(acc[mi][ni], afrag[cur][mi],
                              bfrag[cur][ni >> 1][(ni & 1) * 2],
                              bfrag[cur][ni >> 1][(ni & 1) * 2 + 1]);
                }
            }
        }

        stage++;
        if (stage == NSTAGES) stage = 0;
    }

    // epilogue: direct gmem writes
    int rbase = m0 + warpM + (lane >> 2);
    int cbase = n0 + warpN + (lane & 3) * 2;
    #pragma unroll
    for (int mi = 0; mi < 4; mi++) {
        #pragma unroll
        for (int ni = 0; ni < 4; ni++) {
            float* p0 = out + (size_t)(rbase + mi * 16) * NDIM + cbase + ni * 8;
            float* p1 = p0 + 8 * NDIM;
            *reinterpret_cast<float2*>(p0) = make_float2(acc[mi][ni][0], acc[mi][ni][1]);
            *reinterpret_cast<float2*>(p1) = make_float2(acc[mi][ni][2], acc[mi][ni][3]);
        }
    }
}

// ---------------- launch -----------------------------------------------------
extern "C" void kernel_launch(void* const* d_in, const int* in_sizes, int n_in,
                              void* d_out, int out_size) {
    const float* A = (const float*)d_in[0];   // [4096, 4096] f32
    const float* s = (const float*)d_in[1];   // [32, 4096] f32
    const int* q = (const int*)d_in[2];       // [4096, 512] i32
    float* out = (float*)d_out;               // [4096, 4096] f32

    prep_kernel<<<CONV_BLOCKS + DEQ_BLOCKS, 256>>>(
        reinterpret_cast<const float4*>(A), q, s);

    cudaFuncSetAttribute(gemm_kernel, cudaFuncAttributeMaxDynamicSharedMemorySize,
                         SMEM_TOTAL);
    gemm_kernel<<<dim3(NDIM / 128, MDIM / 128), 256, SMEM_TOTAL>>>(out);
}

// round 11
// speedup vs baseline: 1.0206x; 1.0206x over previous
#include <cuda_runtime.h>
#include <cuda_fp16.h>
#include <cstdint>

// Problem dims (fixed by the dataset)
#define MDIM 4096
#define NDIM 4096
#define KDIM 4096
#define GS   128

// ---------------- scratch (allocation-free rule: __device__ globals) --------
__device__ __half g_Ah[(size_t)MDIM * KDIM];   // A in fp16, row-major [M,K]
__device__ __half g_Wt[(size_t)NDIM * KDIM];   // W^T in fp16, row-major [N,K]

// ---------------- helpers ----------------------------------------------------
__device__ __forceinline__ uint32_t smem_u32(const void* p) {
    uint32_t a;
    asm("{ .reg .u64 t; cvta.to.shared.u64 t, %1; cvt.u32.u64 %0, t; }"
        : "=r"(a) : "l"(p));
    return a;
}

__device__ __forceinline__ uint32_t sw128(uint32_t o) {
    return o ^ ((o >> 3) & 0x70);
}

#define CP_ASYNC16(dst, src) \
    asm volatile("cp.async.cg.shared.global [%0], [%1], 16;" :: "r"(dst), "l"(src) : "memory")

// Pure deferred arrive at async-completion (.noinc: does NOT bump pending count,
// so 128 producer threads complete a phase of a count-128 barrier).
#define CP_ASYNC_MBAR_ARRIVE_NOINC(mbar) \
    asm volatile("cp.async.mbarrier.arrive.noinc.shared.b64 [%0];" :: "r"(mbar) : "memory")

#define MBARRIER_INIT(addr, cnt) \
    asm volatile("mbarrier.init.shared.b64 [%0], %1;" :: "r"(addr), "r"((uint32_t)(cnt)) : "memory")

#define MBARRIER_ARRIVE(addr) \
    asm volatile("mbarrier.arrive.shared.b64 _, [%0];" :: "r"(addr) : "memory")

#define MBARRIER_WAIT_PARITY(mbar_smem_addr, phase_parity) do { \
    uint32_t _mbar = (uint32_t)(mbar_smem_addr); \
    uint32_t _parity = (uint32_t)(phase_parity); \
    uint32_t _done; \
    asm volatile( \
        "{\n\t.reg .pred p;\n\t" \
        "mbarrier.try_wait.parity.acquire.cta.shared::cta.b64 p, [%1], %2;\n\t" \
        "selp.b32 %0, 1, 0, p;\n\t}" \
        : "=r"(_done) : "r"(_mbar), "r"(_parity) : "memory"); \
    if (!_done) { \
        asm volatile( \
            "{\n\t.reg .pred P1;\n\t" \
            "WAIT_LOOP_%=:\n\t" \
            "mbarrier.try_wait.parity.acquire.cta.shared::cta.b64 P1, [%0], %1, 0x989680;\n\t" \
            "@P1 bra.uni WAIT_DONE_%=;\n\t" \
            "bra.uni WAIT_LOOP_%=;\n\t" \
            "WAIT_DONE_%=:\n\t}" \
            :: "r"(_mbar), "r"(_parity) : "memory"); \
    } \
} while (0)

__device__ __forceinline__ void ldsm_x4(uint32_t (&r)[4], uint32_t addr) {
    asm volatile("ldmatrix.sync.aligned.m8n8.x4.shared.b16 {%0,%1,%2,%3}, [%4];"
                 : "=r"(r[0]), "=r"(r[1]), "=r"(r[2]), "=r"(r[3]) : "r"(addr));
}

__device__ __forceinline__ void mma_16816(float (&d)[4], const uint32_t (&a)[4],
                                          const uint32_t b0, const uint32_t b1) {
    asm volatile(
        "mma.sync.aligned.m16n8k16.row.col.f32.f16.f16.f32 "
        "{%0,%1,%2,%3}, {%4,%5,%6,%7}, {%8,%9}, {%0,%1,%2,%3};"
        : "+f"(d[0]), "+f"(d[1]), "+f"(d[2]), "+f"(d[3])
        : "r"(a[0]), "r"(a[1]), "r"(a[2]), "r"(a[3]), "r"(b0), "r"(b1));
}

// ---------------- kernel 1: fused prep ---------------------------------------
static constexpr int CONV_BLOCKS = 8192;
static constexpr int DEQ_BLOCKS = (KDIM / 64) * (NDIM / 64);   // 4096
__global__ void __launch_bounds__(256) prep_kernel(const float4* __restrict__ A,
                                                   const int* __restrict__ q,
                                                   const float* __restrict__ s) {
    int t = threadIdx.x;
    if (blockIdx.x < CONV_BLOCKS) {
        size_t i = (size_t)blockIdx.x * 256 + t;   // 8 floats each
        float4 f0 = A[2 * i];
        float4 f1 = A[2 * i + 1];
        __half2 h[4];
        h[0] = __floats2half2_rn(f0.x, f0.y);
        h[1] = __floats2half2_rn(f0.z, f0.w);
        h[2] = __floats2half2_rn(f1.x, f1.y);
        h[3] = __floats2half2_rn(f1.z, f1.w);
        *reinterpret_cast<uint4*>(g_Ah + 8 * i) = *reinterpret_cast<uint4*>(h);
        return;
    }

    __shared__ float s_sc[64];
    __shared__ __half s_t[64][72];  // [n_local][k_local], padded

    int b = blockIdx.x - CONV_BLOCKS;
    int k0 = (b & 63) * 64;
    int n0 = (b >> 6) * 64;

    if (t < 64) s_sc[t] = s[(size_t)(k0 / GS) * NDIM + n0 + t];
    __syncthreads();

    #pragma unroll
    for (int it = 0; it < 2; it++) {
        int v = t + it * 256;
        int kl = v >> 3;
        int w = v & 7;
        uint32_t qw = (uint32_t)q[(size_t)(k0 + kl) * (NDIM / 8) + (n0 >> 3) + w];
        #pragma unroll
        for (int bb = 0; bb < 8; bb++) {
            int nib = (int)((qw >> (4 * bb)) & 0xFu);
            float val = (float)(nib - 8) * s_sc[w * 8 + bb];
            s_t[w * 8 + bb][kl] = __float2half_rn(val);
        }
    }
    __syncthreads();

    int nl = t >> 2;
    int c = (t & 3) * 16;
    const uint4* src = reinterpret_cast<const uint4*>(&s_t[nl][c]);
    uint4* dst = reinterpret_cast<uint4*>(&g_Wt[(size_t)(n0 + nl) * KDIM + k0 + c]);
    dst[0] = src[0];
    dst[1] = src[1];
}

// ---------------- kernel 2: warp-specialized HMMA f16 GEMM -------------------
// CTA tile 128x128, BK=64. 384 threads: warps 0-7 consume (64x32 warp tiles),
// warps 8-11 produce (cp.async only). 5-stage mbarrier ring, no __syncthreads
// in the mainloop.
static constexpr int BK = 64;
static constexpr int NSTAGES = 5;
static constexpr int NCHUNK = KDIM / BK;            // 64
static constexpr int TILE_BYTES = 128 * BK * 2;     // 16 KB per operand
static constexpr uint32_t STAGE_BYTES = 2 * TILE_BYTES;          // 32 KB
static constexpr uint32_t SMEM_DYN = NSTAGES * STAGE_BYTES + 1024;  // +align pad

__global__ void __launch_bounds__(384, 1)
gemm_kernel(float* __restrict__ out) {
    extern __shared__ char smem[];
    __shared__ uint64_t bars[2 * NSTAGES];   // [full0..full4, empty0..empty4]
    uint32_t sb = (smem_u32(smem) + 1023u) & ~1023u;  // 1KB-align stages for sw128
    uint32_t bar0 = smem_u32(bars);

    int t = threadIdx.x;
    int wid = t >> 5;
    int lane = t & 31;
    int n0 = blockIdx.x * 128;
    int m0 = blockIdx.y * 128;

    if (t == 0) {
        #pragma unroll
        for (int s2 = 0; s2 < NSTAGES; s2++) {
            MBARRIER_INIT(bar0 + s2 * 8, 128);                 // full: 128 producer threads
            MBARRIER_INIT(bar0 + (NSTAGES + s2) * 8, 256);     // empty: 256 consumer threads
        }
    }
    __syncthreads();

    if (wid >= 8) {
        // ---------------- producers (128 threads) ----------------
        int pt = t - 256;               // 0..127
        int stage = 0, phase = 1;       // parity trick: first NSTAGES waits pass
        for (int c = 0; c < NCHUNK; c++) {
            MBARRIER_WAIT_PARITY(bar0 + (NSTAGES + stage) * 8, phase);
            uint32_t a_s = sb + stage * STAGE_BYTES;
            uint32_t b_s = a_s + TILE_BYTES;
            size_t kbase = (size_t)c * BK;
            #pragma unroll
            for (int j = 0; j < 8; j++) {
                int v = pt + 128 * j;          // 0..1023
                int r = v >> 3;                // row 0..127
                int cc = v & 7;                // 16B chunk in 128B row
                uint32_t off = sw128((uint32_t)(r * 128 + cc * 16));
                CP_ASYNC16(a_s + off, g_Ah + (size_t)(m0 + r) * KDIM + kbase + cc * 8);
                CP_ASYNC16(b_s + off, g_Wt + (size_t)(n0 + r) * KDIM + kbase + cc * 8);
            }
            CP_ASYNC_MBAR_ARRIVE_NOINC(bar0 + stage * 8);
            stage++;
            if (stage == NSTAGES) { stage = 0; phase ^= 1; }
        }
        return;
    }

    // ---------------- consumers (256 threads, 8 warps) ----------------
    int warpM = (wid & 1) * 64;
    int warpN = (wid >> 1) * 32;

    int tt = lane >> 3;
    int lr = lane & 7;
    int arow = warpM + (tt & 1) * 8 + lr;
    int akoff = (tt >> 1) * 16;
    int brow = warpN + (tt >> 1) * 8 + lr;
    int bkoff = (tt & 1) * 16;

    float acc[4][4][4];
    #pragma unroll
    for (int mi = 0; mi < 4; mi++)
        #pragma unroll
        for (int ni = 0; ni < 4; ni++)
            #pragma unroll
            for (int e = 0; e < 4; e++) acc[mi][ni][e] = 0.0f;

    int stage = 0, phase = 0;
    for (int i = 0; i < NCHUNK; i++) {
        MBARRIER_WAIT_PARITY(bar0 + stage * 8, phase);

        uint32_t a_s = sb + stage * STAGE_BYTES;
        uint32_t b_s = a_s + TILE_BYTES;

        #pragma unroll
        for (int kk = 0; kk < 4; kk++) {
            uint32_t afrag[4][4];
            #pragma unroll
            for (int mi = 0; mi < 4; mi++) {
                uint32_t off = sw128((uint32_t)((arow + mi * 16) * 128 + kk * 32 + akoff));
                ldsm_x4(afrag[mi], a_s + off);
            }
            uint32_t bfrag[2][4];
            #pragma unroll
            for (int np = 0; np < 2; np++) {
                uint32_t off = sw128((uint32_t)((brow + np * 16) * 128 + kk * 32 + bkoff));
                ldsm_x4(bfrag[np], b_s + off);
            }
            #pragma unroll
            for (int mi = 0; mi < 4; mi++) {
                #pragma unroll
                for (int ni = 0; ni < 4; ni++) {
                    mma_16816(acc[mi][ni], afrag[mi],
                              bfrag[ni >> 1][(ni & 1) * 2],
                              bfrag[ni >> 1][(ni & 1) * 2 + 1]);
                }
            }
        }

        MBARRIER_ARRIVE(bar0 + (NSTAGES + stage) * 8);  // stage free for producers
        stage++;
        if (stage == NSTAGES) { stage = 0; phase ^= 1; }
    }

    // epilogue: direct gmem writes
    int rbase = m0 + warpM + (lane >> 2);
    int cbase = n0 + warpN + (lane & 3) * 2;
    #pragma unroll
    for (int mi = 0; mi < 4; mi++) {
        #pragma unroll
        for (int ni = 0; ni < 4; ni++) {
            float* p0 = out + (size_t)(rbase + mi * 16) * NDIM + cbase + ni * 8;
            float* p1 = p0 + 8 * NDIM;
            *reinterpret_cast<float2*>(p0) = make_float2(acc[mi][ni][0], acc[mi][ni][1]);
            *reinterpret_cast<float2*>(p1) = make_float2(acc[mi][ni][2], acc[mi][ni][3]);
        }
    }
}

// ---------------- launch -----------------------------------------------------
extern "C" void kernel_launch(void* const* d_in, const int* in_sizes, int n_in,
                              void* d_out, int out_size) {
    const float* A = (const float*)d_in[0];   // [4096, 4096] f32
    const float* s = (const float*)d_in[1];   // [32, 4096] f32
    const int* q = (const int*)d_in[2];       // [4096, 512] i32
    float* out = (float*)d_out;               // [4096, 4096] f32

    prep_kernel<<<CONV_BLOCKS + DEQ_BLOCKS, 256>>>(
        reinterpret_cast<const float4*>(A), q, s);

    cudaFuncSetAttribute(gemm_kernel, cudaFuncAttributeMaxDynamicSharedMemorySize,
                         SMEM_DYN);
    gemm_kernel<<<dim3(NDIM / 128, MDIM / 128), 384, SMEM_DYN>>>(out);
}